// round 2
// baseline (speedup 1.0000x reference)
#include <cuda_runtime.h>
#include <cuda_bf16.h>
#include <cstdint>

// ---------------------------------------------------------------------------
// SparseMoE: T=4096 tokens, H=2048, I=8192, E=8, top_k=2
// out[t] = bias + sum_k w[t,k] * gelu(x[t] @ w_in[e_k]) @ w_out[e_k]
// plus router_logits[t, 0:8] appended to output.
// Strategy: fp32 router -> deterministic per-expert compaction ->
//           two sparse tf32 tensor-core GEMM passes -> combine.
// ---------------------------------------------------------------------------

#define T_TOK 4096
#define HDIM  2048
#define IDIM  8192
#define NEXP  8
#define SLOTS 8192   // T_TOK * top_k

// Scratch (device globals: allocation-free kernel_launch)
__device__ float g_hmid[(size_t)SLOTS * IDIM];   // 256 MB
__device__ float g_y[(size_t)SLOTS * HDIM];      // 64 MB
__device__ int   g_tok[SLOTS];                   // slot -> token
__device__ int   g_slot_for[T_TOK * 2];          // (token,k) -> slot
__device__ float g_wts[T_TOK * 2];
__device__ int   g_sel[T_TOK * 2];
__device__ int   g_cnt[NEXP];
__device__ int   g_basearr[NEXP];

// ---------------------------------------------------------------------------
// helpers
// ---------------------------------------------------------------------------
__device__ __forceinline__ uint32_t f2tf32(float f) {
    uint32_t r;
    asm("cvt.rna.tf32.f32 %0, %1;" : "=r"(r) : "f"(f));
    return r;
}

__device__ __forceinline__ void mma_tf32(float* c, const uint32_t* a, const uint32_t* b) {
    asm volatile(
        "mma.sync.aligned.m16n8k8.row.col.f32.tf32.tf32.f32 "
        "{%0,%1,%2,%3}, {%4,%5,%6,%7}, {%8,%9}, {%0,%1,%2,%3};"
        : "+f"(c[0]), "+f"(c[1]), "+f"(c[2]), "+f"(c[3])
        : "r"(a[0]), "r"(a[1]), "r"(a[2]), "r"(a[3]),
          "r"(b[0]), "r"(b[1]));
}

__device__ __forceinline__ float gelu_exact(float x) {
    return 0.5f * x * (1.0f + erff(x * 0.7071067811865476f));
}

// ---------------------------------------------------------------------------
// Kernel 1: router — logits, softmax top-2, normalized weights
// one block per token, 256 threads
// ---------------------------------------------------------------------------
__global__ void router_kernel(const float* __restrict__ x,
                              const float* __restrict__ gw,
                              float* __restrict__ logits_out) {
    int t = blockIdx.x;
    const float* xr = x + (size_t)t * HDIM;

    float acc[NEXP];
#pragma unroll
    for (int e = 0; e < NEXP; e++) acc[e] = 0.f;

    for (int h = threadIdx.x; h < HDIM; h += 256) {
        float xv = xr[h];
        const float4* g = (const float4*)(gw + (size_t)h * NEXP);
        float4 g0 = g[0], g1 = g[1];
        acc[0] += xv * g0.x; acc[1] += xv * g0.y;
        acc[2] += xv * g0.z; acc[3] += xv * g0.w;
        acc[4] += xv * g1.x; acc[5] += xv * g1.y;
        acc[6] += xv * g1.z; acc[7] += xv * g1.w;
    }

    __shared__ float sred[8][NEXP];
    int wid = threadIdx.x >> 5, lane = threadIdx.x & 31;
#pragma unroll
    for (int e = 0; e < NEXP; e++) {
        float v = acc[e];
#pragma unroll
        for (int o = 16; o > 0; o >>= 1) v += __shfl_down_sync(0xffffffffu, v, o);
        if (lane == 0) sred[wid][e] = v;
    }
    __syncthreads();

    if (threadIdx.x == 0) {
        float l[NEXP];
#pragma unroll
        for (int e = 0; e < NEXP; e++) {
            float s = 0.f;
#pragma unroll
            for (int w = 0; w < 8; w++) s += sred[w][e];
            l[e] = s;
            logits_out[(size_t)t * NEXP + e] = s;
        }
        // top-2 (tie -> lowest index, matches jax top_k)
        int i0 = 0;
#pragma unroll
        for (int e = 1; e < NEXP; e++) if (l[e] > l[i0]) i0 = e;
        int i1 = -1;
#pragma unroll
        for (int e = 0; e < NEXP; e++) {
            if (e == i0) continue;
            if (i1 < 0 || l[e] > l[i1]) i1 = e;
        }
        float d = expf(l[i1] - l[i0]);   // <= 1
        float inv = 1.0f / (1.0f + d);
        g_sel[t * 2 + 0] = i0;  g_sel[t * 2 + 1] = i1;
        g_wts[t * 2 + 0] = inv; g_wts[t * 2 + 1] = d * inv;
    }
}

// ---------------------------------------------------------------------------
// Kernel 2: deterministic per-expert compaction (1 block, warp e = expert e)
// ---------------------------------------------------------------------------
__global__ void compact_kernel() {
    int e = threadIdx.x >> 5;
    int lane = threadIdx.x & 31;
    __shared__ int scnt[NEXP], sbase[NEXP];

    // phase 1: count
    int c = 0;
    for (int b = 0; b < T_TOK; b += 32) {
        int t = b + lane;
        bool f = (g_sel[t * 2] == e) || (g_sel[t * 2 + 1] == e);
        unsigned m = __ballot_sync(0xffffffffu, f);
        c += __popc(m);
    }
    if (lane == 0) scnt[e] = c;
    __syncthreads();
    if (threadIdx.x == 0) {
        int s = 0;
        for (int i = 0; i < NEXP; i++) { sbase[i] = s; s += scnt[i]; }
    }
    __syncthreads();
    int base = sbase[e];
    if (lane == 0) { g_cnt[e] = scnt[e]; g_basearr[e] = base; }

    // phase 2: write packed lists
    c = 0;
    for (int b = 0; b < T_TOK; b += 32) {
        int t = b + lane;
        int s0 = g_sel[t * 2], s1 = g_sel[t * 2 + 1];
        bool f0 = (s0 == e), f1 = (s1 == e);
        bool f = f0 || f1;
        unsigned m = __ballot_sync(0xffffffffu, f);
        int off = c + __popc(m & ((1u << lane) - 1u));
        if (f) {
            g_tok[base + off] = t;
            g_slot_for[t * 2 + (f0 ? 0 : 1)] = base + off;
        }
        c += __popc(m);
    }
}

// ---------------------------------------------------------------------------
// Kernel 3/4: tf32 tensor-core GEMM, 128x128x32 tiles, 8 warps (64x32 each).
// PASSA: C[slot] = gelu( x[tok[slot]] @ w_in[e] )   (K=2048, N=8192)
// !PASSA: C[slot] = hmid[slot] @ w_out[e]           (K=8192, N=2048)
// ---------------------------------------------------------------------------
#define SM_STRIDE 136   // 136 % 32 == 8 -> conflict-free fragment access

template <int KTOT, int NTOT, bool PASSA>
__global__ __launch_bounds__(256, 2) void gemm_kernel(
    const float* __restrict__ Aglob,   // x (PASSA) — ignored otherwise
    const float* __restrict__ Bglob)   // w_in or w_out base (all experts)
{
    int e = blockIdx.z;
    int cnt = g_cnt[e];
    int m0 = blockIdx.x * 128;
    if (m0 >= cnt) return;
    int base = g_basearr[e];
    int n0 = blockIdx.y * 128;
    const float* B = Bglob + (size_t)e * KTOT * NTOT;

    __shared__ uint32_t As[32 * SM_STRIDE];
    __shared__ uint32_t Bs[32 * SM_STRIDE];
    __shared__ const float* arow[128];

    int tid = threadIdx.x;
    if (tid < 128) {
        int r = m0 + tid;
        const float* p;
        if (PASSA) {
            int tok = (r < cnt) ? g_tok[base + r] : 0;
            p = Aglob + (size_t)tok * KTOT;
        } else {
            int slot = base + ((r < cnt) ? r : 0);
            if (slot >= SLOTS) slot = 0;
            p = g_hmid + (size_t)slot * KTOT;
        }
        arow[tid] = p;
    }
    __syncthreads();

    int wid = tid >> 5, lane = tid & 31;
    int wm = (wid & 1) * 64;
    int wn = (wid >> 1) * 32;
    int gid = lane >> 2, tig = lane & 3;

    float acc[4][4][4];
#pragma unroll
    for (int i = 0; i < 4; i++)
#pragma unroll
        for (int j = 0; j < 4; j++)
#pragma unroll
            for (int k = 0; k < 4; k++) acc[i][j][k] = 0.f;

#pragma unroll 1
    for (int kt = 0; kt < KTOT / 32; kt++) {
        // --- load A tile (transposed: As[k][m]) ---
#pragma unroll
        for (int j = 0; j < 4; j++) {
            int idx = tid + j * 256;
            int m = idx & 127, kq = idx >> 7;
            float4 v = *(const float4*)(arow[m] + kt * 32 + kq * 4);
            As[(kq * 4 + 0) * SM_STRIDE + m] = f2tf32(v.x);
            As[(kq * 4 + 1) * SM_STRIDE + m] = f2tf32(v.y);
            As[(kq * 4 + 2) * SM_STRIDE + m] = f2tf32(v.z);
            As[(kq * 4 + 3) * SM_STRIDE + m] = f2tf32(v.w);
        }
        // --- load B tile (Bs[k][n]) ---
#pragma unroll
        for (int j = 0; j < 4; j++) {
            int idx = tid + j * 256;
            int n4 = (idx & 31) * 4, kk = idx >> 5;
            float4 v = *(const float4*)(B + (size_t)(kt * 32 + kk) * NTOT + n0 + n4);
            uint4 w;
            w.x = f2tf32(v.x); w.y = f2tf32(v.y);
            w.z = f2tf32(v.z); w.w = f2tf32(v.w);
            *(uint4*)&Bs[kk * SM_STRIDE + n4] = w;
        }
        __syncthreads();

#pragma unroll
        for (int ks = 0; ks < 4; ks++) {
            int kb = ks * 8;
            uint32_t af[4][4], bf[4][2];
#pragma unroll
            for (int ms = 0; ms < 4; ms++) {
                int am = wm + ms * 16 + gid;
                af[ms][0] = As[(kb + tig) * SM_STRIDE + am];
                af[ms][1] = As[(kb + tig) * SM_STRIDE + am + 8];
                af[ms][2] = As[(kb + tig + 4) * SM_STRIDE + am];
                af[ms][3] = As[(kb + tig + 4) * SM_STRIDE + am + 8];
            }
#pragma unroll
            for (int ns = 0; ns < 4; ns++) {
                int bn = wn + ns * 8 + gid;
                bf[ns][0] = Bs[(kb + tig) * SM_STRIDE + bn];
                bf[ns][1] = Bs[(kb + tig + 4) * SM_STRIDE + bn];
            }
#pragma unroll
            for (int ms = 0; ms < 4; ms++)
#pragma unroll
                for (int ns = 0; ns < 4; ns++)
                    mma_tf32(acc[ms][ns], af[ms], bf[ns]);
        }
        __syncthreads();
    }

    // --- epilogue ---
    float* Cg = PASSA ? g_hmid : g_y;
#pragma unroll
    for (int ms = 0; ms < 4; ms++) {
        int r0 = wm + ms * 16 + gid;
        int r1 = r0 + 8;
        bool ok0 = (m0 + r0) < cnt;
        bool ok1 = (m0 + r1) < cnt;
        size_t row0 = (size_t)(base + m0 + r0) * NTOT + n0;
        size_t row1 = (size_t)(base + m0 + r1) * NTOT + n0;
#pragma unroll
        for (int ns = 0; ns < 4; ns++) {
            int c = wn + ns * 8 + tig * 2;
            float v0 = acc[ms][ns][0], v1 = acc[ms][ns][1];
            float v2 = acc[ms][ns][2], v3 = acc[ms][ns][3];
            if (PASSA) {
                v0 = gelu_exact(v0); v1 = gelu_exact(v1);
                v2 = gelu_exact(v2); v3 = gelu_exact(v3);
            }
            if (ok0) *(float2*)(Cg + row0 + c) = make_float2(v0, v1);
            if (ok1) *(float2*)(Cg + row1 + c) = make_float2(v2, v3);
        }
    }
}

// ---------------------------------------------------------------------------
// Kernel 5: combine  out[t,h] = bias[h] + w0*y[slot0,h] + w1*y[slot1,h]
// ---------------------------------------------------------------------------
__global__ void combine_kernel(const float* __restrict__ bias,
                               float* __restrict__ out) {
    int gid = blockIdx.x * 256 + threadIdx.x;   // over T_TOK * 512 float4s
    if (gid >= T_TOK * (HDIM / 4)) return;
    int t = gid >> 9;
    int h4 = gid & 511;
    int s0 = g_slot_for[t * 2], s1 = g_slot_for[t * 2 + 1];
    float w0 = g_wts[t * 2], w1 = g_wts[t * 2 + 1];
    float4 y0 = *(const float4*)(g_y + (size_t)s0 * HDIM + h4 * 4);
    float4 y1 = *(const float4*)(g_y + (size_t)s1 * HDIM + h4 * 4);
    float4 b = *(const float4*)(bias + h4 * 4);
    float4 o;
    o.x = b.x + w0 * y0.x + w1 * y1.x;
    o.y = b.y + w0 * y0.y + w1 * y1.y;
    o.z = b.z + w0 * y0.z + w1 * y1.z;
    o.w = b.w + w0 * y0.w + w1 * y1.w;
    *(float4*)(out + (size_t)t * HDIM + h4 * 4) = o;
}

// ---------------------------------------------------------------------------
// launch
// ---------------------------------------------------------------------------
extern "C" void kernel_launch(void* const* d_in, const int* in_sizes, int n_in,
                              void* d_out, int out_size) {
    const float* x     = (const float*)d_in[0];   // [2,2048,2048]
    const float* gw    = (const float*)d_in[1];   // [2048,8]
    const float* w_in  = (const float*)d_in[2];   // [8,2048,8192]
    const float* w_out = (const float*)d_in[3];   // [8,8192,2048]
    const float* bias  = (const float*)d_in[4];   // [2048]
    (void)in_sizes; (void)n_in; (void)out_size;

    float* out    = (float*)d_out;
    float* logits = out + (size_t)T_TOK * HDIM;   // router_logits appended

    router_kernel<<<T_TOK, 256>>>(x, gw, logits);
    compact_kernel<<<1, 256>>>();

    dim3 ga(T_TOK / 128, IDIM / 128, NEXP);       // (32, 64, 8)
    gemm_kernel<HDIM, IDIM, true><<<ga, 256>>>(x, w_in);

    dim3 gb(T_TOK / 128, HDIM / 128, NEXP);       // (32, 16, 8)
    gemm_kernel<IDIM, HDIM, false><<<gb, 256>>>(nullptr, w_out);

    combine_kernel<<<(T_TOK * (HDIM / 4) + 255) / 256, 256>>>(bias, out);
}

// round 3
// speedup vs baseline: 1.0006x; 1.0006x over previous
#include <cuda_runtime.h>
#include <cuda_bf16.h>
#include <cstdint>

// ---------------------------------------------------------------------------
// SparseMoE: T=4096 tokens, H=2048, I=8192, E=8, top_k=2
// out[t] = bias + sum_k w[t,k] * gelu(x[t] @ w_in[e_k]) @ w_out[e_k]
// plus router_logits[t, 0:8] appended to output.
// Strategy: fp32 router -> deterministic per-expert compaction ->
//           two sparse tf32 tensor-core GEMM passes -> combine.
// ---------------------------------------------------------------------------

#define T_TOK 4096
#define HDIM  2048
#define IDIM  8192
#define NEXP  8
#define SLOTS 8192   // T_TOK * top_k

// Scratch (device globals: allocation-free kernel_launch)
__device__ float g_hmid[(size_t)SLOTS * IDIM];   // 256 MB
__device__ float g_y[(size_t)SLOTS * HDIM];      // 64 MB
__device__ int   g_tok[SLOTS];                   // slot -> token
__device__ int   g_slot_for[T_TOK * 2];          // (token,k) -> slot
__device__ float g_wts[T_TOK * 2];
__device__ int   g_sel[T_TOK * 2];
__device__ int   g_cnt[NEXP];
__device__ int   g_basearr[NEXP];

// ---------------------------------------------------------------------------
// helpers
// ---------------------------------------------------------------------------
__device__ __forceinline__ uint32_t f2tf32(float f) {
    uint32_t r;
    asm("cvt.rna.tf32.f32 %0, %1;" : "=r"(r) : "f"(f));
    return r;
}

__device__ __forceinline__ void mma_tf32(float* c, const uint32_t* a, const uint32_t* b) {
    asm volatile(
        "mma.sync.aligned.m16n8k8.row.col.f32.tf32.tf32.f32 "
        "{%0,%1,%2,%3}, {%4,%5,%6,%7}, {%8,%9}, {%0,%1,%2,%3};"
        : "+f"(c[0]), "+f"(c[1]), "+f"(c[2]), "+f"(c[3])
        : "r"(a[0]), "r"(a[1]), "r"(a[2]), "r"(a[3]),
          "r"(b[0]), "r"(b[1]));
}

__device__ __forceinline__ float gelu_exact(float x) {
    return 0.5f * x * (1.0f + erff(x * 0.7071067811865476f));
}

// ---------------------------------------------------------------------------
// Kernel 1: router — logits, softmax top-2, normalized weights
// one block per token, 256 threads
// ---------------------------------------------------------------------------
__global__ void router_kernel(const float* __restrict__ x,
                              const float* __restrict__ gw,
                              float* __restrict__ logits_out) {
    int t = blockIdx.x;
    const float* xr = x + (size_t)t * HDIM;

    float acc[NEXP];
#pragma unroll
    for (int e = 0; e < NEXP; e++) acc[e] = 0.f;

    for (int h = threadIdx.x; h < HDIM; h += 256) {
        float xv = xr[h];
        const float4* g = (const float4*)(gw + (size_t)h * NEXP);
        float4 g0 = g[0], g1 = g[1];
        acc[0] += xv * g0.x; acc[1] += xv * g0.y;
        acc[2] += xv * g0.z; acc[3] += xv * g0.w;
        acc[4] += xv * g1.x; acc[5] += xv * g1.y;
        acc[6] += xv * g1.z; acc[7] += xv * g1.w;
    }

    __shared__ float sred[8][NEXP];
    int wid = threadIdx.x >> 5, lane = threadIdx.x & 31;
#pragma unroll
    for (int e = 0; e < NEXP; e++) {
        float v = acc[e];
#pragma unroll
        for (int o = 16; o > 0; o >>= 1) v += __shfl_down_sync(0xffffffffu, v, o);
        if (lane == 0) sred[wid][e] = v;
    }
    __syncthreads();

    if (threadIdx.x == 0) {
        float l[NEXP];
#pragma unroll
        for (int e = 0; e < NEXP; e++) {
            float s = 0.f;
#pragma unroll
            for (int w = 0; w < 8; w++) s += sred[w][e];
            l[e] = s;
            logits_out[(size_t)t * NEXP + e] = s;
        }
        // top-2 (tie -> lowest index, matches jax top_k)
        int i0 = 0;
#pragma unroll
        for (int e = 1; e < NEXP; e++) if (l[e] > l[i0]) i0 = e;
        int i1 = -1;
#pragma unroll
        for (int e = 0; e < NEXP; e++) {
            if (e == i0) continue;
            if (i1 < 0 || l[e] > l[i1]) i1 = e;
        }
        float d = expf(l[i1] - l[i0]);   // <= 1
        float inv = 1.0f / (1.0f + d);
        g_sel[t * 2 + 0] = i0;  g_sel[t * 2 + 1] = i1;
        g_wts[t * 2 + 0] = inv; g_wts[t * 2 + 1] = d * inv;
    }
}

// ---------------------------------------------------------------------------
// Kernel 2: deterministic per-expert compaction (1 block, warp e = expert e)
// ---------------------------------------------------------------------------
__global__ void compact_kernel() {
    int e = threadIdx.x >> 5;
    int lane = threadIdx.x & 31;
    __shared__ int scnt[NEXP], sbase[NEXP];

    // phase 1: count
    int c = 0;
    for (int b = 0; b < T_TOK; b += 32) {
        int t = b + lane;
        bool f = (g_sel[t * 2] == e) || (g_sel[t * 2 + 1] == e);
        unsigned m = __ballot_sync(0xffffffffu, f);
        c += __popc(m);
    }
    if (lane == 0) scnt[e] = c;
    __syncthreads();
    if (threadIdx.x == 0) {
        int s = 0;
        for (int i = 0; i < NEXP; i++) { sbase[i] = s; s += scnt[i]; }
    }
    __syncthreads();
    int base = sbase[e];
    if (lane == 0) { g_cnt[e] = scnt[e]; g_basearr[e] = base; }

    // phase 2: write packed lists
    c = 0;
    for (int b = 0; b < T_TOK; b += 32) {
        int t = b + lane;
        int s0 = g_sel[t * 2], s1 = g_sel[t * 2 + 1];
        bool f0 = (s0 == e), f1 = (s1 == e);
        bool f = f0 || f1;
        unsigned m = __ballot_sync(0xffffffffu, f);
        int off = c + __popc(m & ((1u << lane) - 1u));
        if (f) {
            g_tok[base + off] = t;
            g_slot_for[t * 2 + (f0 ? 0 : 1)] = base + off;
        }
        c += __popc(m);
    }
}

// ---------------------------------------------------------------------------
// Kernel 3/4: tf32 tensor-core GEMM, 128x128x32 tiles, 8 warps (64x32 each).
// PASSA: C[slot] = gelu( x[tok[slot]] @ w_in[e] )   (K=2048, N=8192)
// !PASSA: C[slot] = hmid[slot] @ w_out[e]           (K=8192, N=2048)
// ---------------------------------------------------------------------------
#define SM_STRIDE 136   // 136 % 32 == 8 -> conflict-free fragment access

template <int KTOT, int NTOT, bool PASSA>
__global__ __launch_bounds__(256, 2) void gemm_kernel(
    const float* __restrict__ Aglob,   // x (PASSA) — ignored otherwise
    const float* __restrict__ Bglob)   // w_in or w_out base (all experts)
{
    int e = blockIdx.z;
    int cnt = g_cnt[e];
    int m0 = blockIdx.x * 128;
    if (m0 >= cnt) return;
    int base = g_basearr[e];
    int n0 = blockIdx.y * 128;
    const float* B = Bglob + (size_t)e * KTOT * NTOT;

    __shared__ uint32_t As[32 * SM_STRIDE];
    __shared__ uint32_t Bs[32 * SM_STRIDE];
    __shared__ const float* arow[128];

    int tid = threadIdx.x;
    if (tid < 128) {
        int r = m0 + tid;
        const float* p;
        if (PASSA) {
            int tok = (r < cnt) ? g_tok[base + r] : 0;
            p = Aglob + (size_t)tok * KTOT;
        } else {
            int slot = base + ((r < cnt) ? r : 0);
            if (slot >= SLOTS) slot = 0;
            p = g_hmid + (size_t)slot * KTOT;
        }
        arow[tid] = p;
    }
    __syncthreads();

    int wid = tid >> 5, lane = tid & 31;
    int wm = (wid & 1) * 64;
    int wn = (wid >> 1) * 32;
    int gid = lane >> 2, tig = lane & 3;

    float acc[4][4][4];
#pragma unroll
    for (int i = 0; i < 4; i++)
#pragma unroll
        for (int j = 0; j < 4; j++)
#pragma unroll
            for (int k = 0; k < 4; k++) acc[i][j][k] = 0.f;

#pragma unroll 1
    for (int kt = 0; kt < KTOT / 32; kt++) {
        // --- load A tile (transposed: As[k][m]) ---
#pragma unroll
        for (int j = 0; j < 4; j++) {
            int idx = tid + j * 256;
            int m = idx & 127, kq = idx >> 7;
            float4 v = *(const float4*)(arow[m] + kt * 32 + kq * 4);
            As[(kq * 4 + 0) * SM_STRIDE + m] = f2tf32(v.x);
            As[(kq * 4 + 1) * SM_STRIDE + m] = f2tf32(v.y);
            As[(kq * 4 + 2) * SM_STRIDE + m] = f2tf32(v.z);
            As[(kq * 4 + 3) * SM_STRIDE + m] = f2tf32(v.w);
        }
        // --- load B tile (Bs[k][n]) ---
#pragma unroll
        for (int j = 0; j < 4; j++) {
            int idx = tid + j * 256;
            int n4 = (idx & 31) * 4, kk = idx >> 5;
            float4 v = *(const float4*)(B + (size_t)(kt * 32 + kk) * NTOT + n0 + n4);
            uint4 w;
            w.x = f2tf32(v.x); w.y = f2tf32(v.y);
            w.z = f2tf32(v.z); w.w = f2tf32(v.w);
            *(uint4*)&Bs[kk * SM_STRIDE + n4] = w;
        }
        __syncthreads();

#pragma unroll
        for (int ks = 0; ks < 4; ks++) {
            int kb = ks * 8;
            uint32_t af[4][4], bf[4][2];
#pragma unroll
            for (int ms = 0; ms < 4; ms++) {
                int am = wm + ms * 16 + gid;
                af[ms][0] = As[(kb + tig) * SM_STRIDE + am];
                af[ms][1] = As[(kb + tig) * SM_STRIDE + am + 8];
                af[ms][2] = As[(kb + tig + 4) * SM_STRIDE + am];
                af[ms][3] = As[(kb + tig + 4) * SM_STRIDE + am + 8];
            }
#pragma unroll
            for (int ns = 0; ns < 4; ns++) {
                int bn = wn + ns * 8 + gid;
                bf[ns][0] = Bs[(kb + tig) * SM_STRIDE + bn];
                bf[ns][1] = Bs[(kb + tig + 4) * SM_STRIDE + bn];
            }
#pragma unroll
            for (int ms = 0; ms < 4; ms++)
#pragma unroll
                for (int ns = 0; ns < 4; ns++)
                    mma_tf32(acc[ms][ns], af[ms], bf[ns]);
        }
        __syncthreads();
    }

    // --- epilogue ---
    float* Cg = PASSA ? g_hmid : g_y;
#pragma unroll
    for (int ms = 0; ms < 4; ms++) {
        int r0 = wm + ms * 16 + gid;
        int r1 = r0 + 8;
        bool ok0 = (m0 + r0) < cnt;
        bool ok1 = (m0 + r1) < cnt;
        size_t row0 = (size_t)(base + m0 + r0) * NTOT + n0;
        size_t row1 = (size_t)(base + m0 + r1) * NTOT + n0;
#pragma unroll
        for (int ns = 0; ns < 4; ns++) {
            int c = wn + ns * 8 + tig * 2;
            float v0 = acc[ms][ns][0], v1 = acc[ms][ns][1];
            float v2 = acc[ms][ns][2], v3 = acc[ms][ns][3];
            if (PASSA) {
                v0 = gelu_exact(v0); v1 = gelu_exact(v1);
                v2 = gelu_exact(v2); v3 = gelu_exact(v3);
            }
            if (ok0) *(float2*)(Cg + row0 + c) = make_float2(v0, v1);
            if (ok1) *(float2*)(Cg + row1 + c) = make_float2(v2, v3);
        }
    }
}

// ---------------------------------------------------------------------------
// Kernel 5: combine  out[t,h] = bias[h] + w0*y[slot0,h] + w1*y[slot1,h]
// ---------------------------------------------------------------------------
__global__ void combine_kernel(const float* __restrict__ bias,
                               float* __restrict__ out) {
    int gid = blockIdx.x * 256 + threadIdx.x;   // over T_TOK * 512 float4s
    if (gid >= T_TOK * (HDIM / 4)) return;
    int t = gid >> 9;
    int h4 = gid & 511;
    int s0 = g_slot_for[t * 2], s1 = g_slot_for[t * 2 + 1];
    float w0 = g_wts[t * 2], w1 = g_wts[t * 2 + 1];
    float4 y0 = *(const float4*)(g_y + (size_t)s0 * HDIM + h4 * 4);
    float4 y1 = *(const float4*)(g_y + (size_t)s1 * HDIM + h4 * 4);
    float4 b = *(const float4*)(bias + h4 * 4);
    float4 o;
    o.x = b.x + w0 * y0.x + w1 * y1.x;
    o.y = b.y + w0 * y0.y + w1 * y1.y;
    o.z = b.z + w0 * y0.z + w1 * y1.z;
    o.w = b.w + w0 * y0.w + w1 * y1.w;
    *(float4*)(out + (size_t)t * HDIM + h4 * 4) = o;
}

// ---------------------------------------------------------------------------
// launch
// ---------------------------------------------------------------------------
extern "C" void kernel_launch(void* const* d_in, const int* in_sizes, int n_in,
                              void* d_out, int out_size) {
    const float* x     = (const float*)d_in[0];   // [2,2048,2048]
    const float* gw    = (const float*)d_in[1];   // [2048,8]
    const float* w_in  = (const float*)d_in[2];   // [8,2048,8192]
    const float* w_out = (const float*)d_in[3];   // [8,8192,2048]
    const float* bias  = (const float*)d_in[4];   // [2048]
    (void)in_sizes; (void)n_in; (void)out_size;

    float* out    = (float*)d_out;
    float* logits = out + (size_t)T_TOK * HDIM;   // router_logits appended

    router_kernel<<<T_TOK, 256>>>(x, gw, logits);
    compact_kernel<<<1, 256>>>();

    dim3 ga(T_TOK / 128, IDIM / 128, NEXP);       // (32, 64, 8)
    gemm_kernel<HDIM, IDIM, true><<<ga, 256>>>(x, w_in);

    dim3 gb(T_TOK / 128, HDIM / 128, NEXP);       // (32, 16, 8)
    gemm_kernel<IDIM, HDIM, false><<<gb, 256>>>(nullptr, w_out);

    combine_kernel<<<(T_TOK * (HDIM / 4) + 255) / 256, 256>>>(bias, out);
}

// round 7
// speedup vs baseline: 1.3577x; 1.3568x over previous
#include <cuda_runtime.h>
#include <cstdint>

// ---------------------------------------------------------------------------
// SparseMoE: T=4096 tokens, H=2048, I=8192, E=8, top_k=2
// Round 6: tcgen05 unavailable (PTX target is compute_103, not 103a).
// Optimize the legacy mma.sync(tf32) path instead:
//   - 128x256 block, 64x64 warp tiles (1.5x less LDS per FLOP)
//   - cp.async 3-stage pipeline (kills the LDG->reg->cvt->STS chain)
//   - cvt.rna.tf32 applied to fragments post-LDS (ALU pipe, overlapped)
// ---------------------------------------------------------------------------

#define T_TOK 4096
#define HDIM  2048
#define IDIM  8192
#define NEXP  8
#define SLOTS 8192

__device__ float g_hmid[(size_t)SLOTS * IDIM];   // 256 MB
__device__ float g_y[(size_t)SLOTS * HDIM];      // 64 MB
__device__ int   g_tok[SLOTS];
__device__ int   g_slot_for[T_TOK * 2];
__device__ float g_wts[T_TOK * 2];
__device__ int   g_sel[T_TOK * 2];
__device__ int   g_cnt[NEXP];
__device__ int   g_basearr[NEXP];

// ---------------------------------------------------------------------------
// helpers
// ---------------------------------------------------------------------------
__device__ __forceinline__ uint32_t smem_u32(const void* p) {
    uint32_t a;
    asm("{ .reg .u64 t; cvta.to.shared.u64 t, %1; cvt.u32.u64 %0, t; }"
        : "=r"(a) : "l"(p));
    return a;
}
__device__ __forceinline__ uint32_t f2tf32(float f) {
    uint32_t r;
    asm("cvt.rna.tf32.f32 %0, %1;" : "=r"(r) : "f"(f));
    return r;
}
__device__ __forceinline__ void mma_tf32(float* c, const uint32_t* a, const uint32_t* b) {
    asm volatile(
        "mma.sync.aligned.m16n8k8.row.col.f32.tf32.tf32.f32 "
        "{%0,%1,%2,%3}, {%4,%5,%6,%7}, {%8,%9}, {%0,%1,%2,%3};"
        : "+f"(c[0]), "+f"(c[1]), "+f"(c[2]), "+f"(c[3])
        : "r"(a[0]), "r"(a[1]), "r"(a[2]), "r"(a[3]),
          "r"(b[0]), "r"(b[1]));
}
__device__ __forceinline__ float gelu_exact(float x) {
    return 0.5f * x * (1.0f + erff(x * 0.7071067811865476f));
}

#define CP_ASYNC16(dst, src) \
    asm volatile("cp.async.cg.shared.global [%0], [%1], 16;" :: "r"(dst), "l"(src))
#define CP_COMMIT() asm volatile("cp.async.commit_group;" ::: "memory")
#define CP_WAIT1()  asm volatile("cp.async.wait_group 1;" ::: "memory")

// ---------------------------------------------------------------------------
// Kernel 1: router
// ---------------------------------------------------------------------------
__global__ void router_kernel(const float* __restrict__ x,
                              const float* __restrict__ gw,
                              float* __restrict__ logits_out) {
    int t = blockIdx.x;
    const float* xr = x + (size_t)t * HDIM;

    float acc[NEXP];
#pragma unroll
    for (int e = 0; e < NEXP; e++) acc[e] = 0.f;

    for (int h = threadIdx.x; h < HDIM; h += 256) {
        float xv = xr[h];
        const float4* g = (const float4*)(gw + (size_t)h * NEXP);
        float4 g0 = g[0], g1 = g[1];
        acc[0] += xv * g0.x; acc[1] += xv * g0.y;
        acc[2] += xv * g0.z; acc[3] += xv * g0.w;
        acc[4] += xv * g1.x; acc[5] += xv * g1.y;
        acc[6] += xv * g1.z; acc[7] += xv * g1.w;
    }

    __shared__ float sred[8][NEXP];
    int wid = threadIdx.x >> 5, lane = threadIdx.x & 31;
#pragma unroll
    for (int e = 0; e < NEXP; e++) {
        float v = acc[e];
#pragma unroll
        for (int o = 16; o > 0; o >>= 1) v += __shfl_down_sync(0xffffffffu, v, o);
        if (lane == 0) sred[wid][e] = v;
    }
    __syncthreads();

    if (threadIdx.x == 0) {
        float l[NEXP];
#pragma unroll
        for (int e = 0; e < NEXP; e++) {
            float s = 0.f;
#pragma unroll
            for (int w = 0; w < 8; w++) s += sred[w][e];
            l[e] = s;
            logits_out[(size_t)t * NEXP + e] = s;
        }
        int i0 = 0;
#pragma unroll
        for (int e = 1; e < NEXP; e++) if (l[e] > l[i0]) i0 = e;
        int i1 = -1;
#pragma unroll
        for (int e = 0; e < NEXP; e++) {
            if (e == i0) continue;
            if (i1 < 0 || l[e] > l[i1]) i1 = e;
        }
        float d = expf(l[i1] - l[i0]);
        float inv = 1.0f / (1.0f + d);
        g_sel[t * 2 + 0] = i0;  g_sel[t * 2 + 1] = i1;
        g_wts[t * 2 + 0] = inv; g_wts[t * 2 + 1] = d * inv;
    }
}

// ---------------------------------------------------------------------------
// Kernel 2: deterministic compaction
// ---------------------------------------------------------------------------
__global__ void compact_kernel() {
    int e = threadIdx.x >> 5;
    int lane = threadIdx.x & 31;
    __shared__ int scnt[NEXP], sbase[NEXP];

    int c = 0;
    for (int b = 0; b < T_TOK; b += 32) {
        int t = b + lane;
        bool f = (g_sel[t * 2] == e) || (g_sel[t * 2 + 1] == e);
        unsigned m = __ballot_sync(0xffffffffu, f);
        c += __popc(m);
    }
    if (lane == 0) scnt[e] = c;
    __syncthreads();
    if (threadIdx.x == 0) {
        int s = 0;
        for (int i = 0; i < NEXP; i++) { sbase[i] = s; s += scnt[i]; }
    }
    __syncthreads();
    int base = sbase[e];
    if (lane == 0) { g_cnt[e] = scnt[e]; g_basearr[e] = base; }

    c = 0;
    for (int b = 0; b < T_TOK; b += 32) {
        int t = b + lane;
        int s0 = g_sel[t * 2], s1 = g_sel[t * 2 + 1];
        bool f0 = (s0 == e), f1 = (s1 == e);
        bool f = f0 || f1;
        unsigned m = __ballot_sync(0xffffffffu, f);
        int off = c + __popc(m & ((1u << lane) - 1u));
        if (f) {
            g_tok[base + off] = t;
            g_slot_for[t * 2 + (f0 ? 0 : 1)] = base + off;
        }
        c += __popc(m);
    }
}

// ---------------------------------------------------------------------------
// Kernel 3/4: tf32 mma.sync GEMM, 128(M)x256(N)x32(K) block, 8 warps (64x64),
// cp.async 3-stage pipeline, fragments converted post-LDS via cvt.rna.
//   A smem: [128 rows][36 floats]  (144B rows; bank = 4*gid+tig, conflict-free)
//   B smem: [32 rows][260 floats]  (1040B rows; bank = 4*tig+gid, conflict-free)
// ---------------------------------------------------------------------------
#define BM 128
#define BN 256
#define BK 32
#define A_ROW_F 36
#define B_ROW_F 260
#define A_BYTES (BM * A_ROW_F * 4)                 // 18432
#define B_OFF   A_BYTES
#define STAGE   (A_BYTES + BK * B_ROW_F * 4)       // 51712
#define NSTAGE  3
#define SMEM_SZ (NSTAGE * STAGE)                   // 155136

template <int KTOT, int NTOT, bool PASSA>
__global__ __launch_bounds__(256, 1) void gemm_cp(const float* __restrict__ Aglob,
                                                  const float* __restrict__ Bglob) {
    constexpr int NT = KTOT / BK;

    extern __shared__ char smem[];
    const int e = blockIdx.z;
    const int cnt = g_cnt[e];
    const int m0 = blockIdx.x * BM;
    if (m0 >= cnt) return;
    const int base = g_basearr[e];
    const int n0 = blockIdx.y * BN;
    const float* Bsrc = Bglob + (size_t)e * KTOT * NTOT;

    const uint32_t sb32 = smem_u32(smem);
    const int tid = threadIdx.x;

    // ---- loader geometry (registers, constant across K) ----
    const float* asrc[4];
    uint32_t adst[4];
    {
        int c8 = tid & 7;                      // 16B chunk within 128B row
#pragma unroll
        for (int i = 0; i < 4; i++) {
            int m = (tid >> 3) + i * 32;       // 0..127
            int r = m0 + m;
            const float* rowp;
            if (PASSA) {
                int tok = g_tok[base + ((r < cnt) ? r : 0)];
                rowp = Aglob + (size_t)tok * KTOT;
            } else {
                int slot = base + ((r < cnt) ? r : 0);
                rowp = g_hmid + (size_t)slot * KTOT;
            }
            asrc[i] = rowp + c8 * 4;
            adst[i] = (uint32_t)(m * (A_ROW_F * 4) + c8 * 16);
        }
    }
    const float* bsrc[8];
    uint32_t bdst[8];
    {
        int c = tid & 63;                      // 16B chunk within 1KB row
#pragma unroll
        for (int i = 0; i < 8; i++) {
            int k = (tid >> 6) + i * 4;        // 0..31
            bsrc[i] = Bsrc + (size_t)k * NTOT + n0 + c * 4;
            bdst[i] = (uint32_t)(B_OFF + k * (B_ROW_F * 4) + c * 16);
        }
    }

    auto issue = [&](int kt, int s) {
        uint32_t so = sb32 + s * STAGE;
#pragma unroll
        for (int i = 0; i < 4; i++)
            CP_ASYNC16(so + adst[i], asrc[i] + kt * BK);
#pragma unroll
        for (int i = 0; i < 8; i++)
            CP_ASYNC16(so + bdst[i], bsrc[i] + (size_t)kt * BK * NTOT);
    };

    issue(0, 0); CP_COMMIT();
    issue(1, 1); CP_COMMIT();

    const int wid = tid >> 5, lane = tid & 31;
    const int wm = (wid & 1) * 64;
    const int wn = (wid >> 1) * 64;
    const int gid = lane >> 2, tig = lane & 3;

    float acc[4][8][4];
#pragma unroll
    for (int i = 0; i < 4; i++)
#pragma unroll
        for (int j = 0; j < 8; j++)
#pragma unroll
            for (int k = 0; k < 4; k++) acc[i][j][k] = 0.f;

#pragma unroll 1
    for (int kt = 0; kt < NT; kt++) {
        CP_WAIT1();              // stage kt resident
        __syncthreads();         // all warps done with stage kt-1, loads visible
        if (kt + 2 < NT) issue(kt + 2, (kt + 2) % NSTAGE);
        CP_COMMIT();             // always commit (keeps group arithmetic uniform)

        const int s = kt % NSTAGE;
        const float* As = (const float*)(smem + s * STAGE);
        const float* Bs = (const float*)(smem + s * STAGE + B_OFF);

#pragma unroll
        for (int ks = 0; ks < 4; ks++) {
            const int kb = ks * 8;
            uint32_t af[4][4], bf[8][2];
#pragma unroll
            for (int ms = 0; ms < 4; ms++) {
                int am = wm + ms * 16 + gid;
                af[ms][0] = f2tf32(As[am * A_ROW_F + kb + tig]);
                af[ms][1] = f2tf32(As[(am + 8) * A_ROW_F + kb + tig]);
                af[ms][2] = f2tf32(As[am * A_ROW_F + kb + tig + 4]);
                af[ms][3] = f2tf32(As[(am + 8) * A_ROW_F + kb + tig + 4]);
            }
#pragma unroll
            for (int ns = 0; ns < 8; ns++) {
                int bn = wn + ns * 8 + gid;
                bf[ns][0] = f2tf32(Bs[(kb + tig) * B_ROW_F + bn]);
                bf[ns][1] = f2tf32(Bs[(kb + tig + 4) * B_ROW_F + bn]);
            }
#pragma unroll
            for (int ms = 0; ms < 4; ms++)
#pragma unroll
                for (int ns = 0; ns < 8; ns++)
                    mma_tf32(acc[ms][ns], af[ms], bf[ns]);
        }
    }

    // ---- epilogue: registers -> gmem ----
    float* Cg = PASSA ? g_hmid : g_y;
#pragma unroll
    for (int ms = 0; ms < 4; ms++) {
        int r0 = wm + ms * 16 + gid;
        int r1 = r0 + 8;
        bool ok0 = (m0 + r0) < cnt;
        bool ok1 = (m0 + r1) < cnt;
        size_t row0 = (size_t)(base + m0 + r0) * NTOT + n0;
        size_t row1 = (size_t)(base + m0 + r1) * NTOT + n0;
#pragma unroll
        for (int ns = 0; ns < 8; ns++) {
            int c = wn + ns * 8 + tig * 2;
            float v0 = acc[ms][ns][0], v1 = acc[ms][ns][1];
            float v2 = acc[ms][ns][2], v3 = acc[ms][ns][3];
            if (PASSA) {
                v0 = gelu_exact(v0); v1 = gelu_exact(v1);
                v2 = gelu_exact(v2); v3 = gelu_exact(v3);
            }
            if (ok0) *(float2*)(Cg + row0 + c) = make_float2(v0, v1);
            if (ok1) *(float2*)(Cg + row1 + c) = make_float2(v2, v3);
        }
    }
}

// ---------------------------------------------------------------------------
// Kernel 5: combine
// ---------------------------------------------------------------------------
__global__ void combine_kernel(const float* __restrict__ bias,
                               float* __restrict__ out) {
    int gid = blockIdx.x * 256 + threadIdx.x;
    if (gid >= T_TOK * (HDIM / 4)) return;
    int t = gid >> 9;
    int h4 = gid & 511;
    int s0 = g_slot_for[t * 2], s1 = g_slot_for[t * 2 + 1];
    float w0 = g_wts[t * 2], w1 = g_wts[t * 2 + 1];
    float4 y0 = *(const float4*)(g_y + (size_t)s0 * HDIM + h4 * 4);
    float4 y1 = *(const float4*)(g_y + (size_t)s1 * HDIM + h4 * 4);
    float4 b = *(const float4*)(bias + h4 * 4);
    float4 o;
    o.x = b.x + w0 * y0.x + w1 * y1.x;
    o.y = b.y + w0 * y0.y + w1 * y1.y;
    o.z = b.z + w0 * y0.z + w1 * y1.z;
    o.w = b.w + w0 * y0.w + w1 * y1.w;
    *(float4*)(out + (size_t)t * HDIM + h4 * 4) = o;
}

// ---------------------------------------------------------------------------
// launch
// ---------------------------------------------------------------------------
extern "C" void kernel_launch(void* const* d_in, const int* in_sizes, int n_in,
                              void* d_out, int out_size) {
    const float* x     = (const float*)d_in[0];   // [2,2048,2048]
    const float* gw    = (const float*)d_in[1];   // [2048,8]
    const float* w_in  = (const float*)d_in[2];   // [8,2048,8192]
    const float* w_out = (const float*)d_in[3];   // [8,8192,2048]
    const float* bias  = (const float*)d_in[4];   // [2048]
    (void)in_sizes; (void)n_in; (void)out_size;

    float* out    = (float*)d_out;
    float* logits = out + (size_t)T_TOK * HDIM;

    cudaFuncSetAttribute(gemm_cp<HDIM, IDIM, true>,
                         cudaFuncAttributeMaxDynamicSharedMemorySize, SMEM_SZ);
    cudaFuncSetAttribute(gemm_cp<IDIM, HDIM, false>,
                         cudaFuncAttributeMaxDynamicSharedMemorySize, SMEM_SZ);

    router_kernel<<<T_TOK, 256>>>(x, gw, logits);
    compact_kernel<<<1, 256>>>();

    dim3 ga(T_TOK / BM, IDIM / BN, NEXP);         // (32, 32, 8)
    gemm_cp<HDIM, IDIM, true><<<ga, 256, SMEM_SZ>>>(x, w_in);

    dim3 gb(T_TOK / BM, HDIM / BN, NEXP);         // (32, 8, 8)
    gemm_cp<IDIM, HDIM, false><<<gb, 256, SMEM_SZ>>>(nullptr, w_out);

    combine_kernel<<<(T_TOK * (HDIM / 4) + 255) / 256, 256>>>(bias, out);
}

// round 11
// speedup vs baseline: 1.4336x; 1.0559x over previous
#include <cuda_runtime.h>
#include <cstdint>

// ---------------------------------------------------------------------------
// SparseMoE: T=4096 tokens, H=2048, I=8192, E=8, top_k=2
// Round 7: occupancy fix. 128-thread CTAs (4 warps, 128x128 block tile,
// 64x64 warp tiles), 3-stage cp.async pipeline, 106KB smem -> 2 CTAs/SM.
// Two co-resident CTAs hide each other's barrier/pipeline stalls.
// ---------------------------------------------------------------------------

#define T_TOK 4096
#define HDIM  2048
#define IDIM  8192
#define NEXP  8
#define SLOTS 8192

__device__ float g_hmid[(size_t)SLOTS * IDIM];   // 256 MB
__device__ float g_y[(size_t)SLOTS * HDIM];      // 64 MB
__device__ int   g_tok[SLOTS];
__device__ int   g_slot_for[T_TOK * 2];
__device__ float g_wts[T_TOK * 2];
__device__ int   g_sel[T_TOK * 2];
__device__ int   g_cnt[NEXP];
__device__ int   g_basearr[NEXP];

// ---------------------------------------------------------------------------
// helpers
// ---------------------------------------------------------------------------
__device__ __forceinline__ uint32_t smem_u32(const void* p) {
    uint32_t a;
    asm("{ .reg .u64 t; cvta.to.shared.u64 t, %1; cvt.u32.u64 %0, t; }"
        : "=r"(a) : "l"(p));
    return a;
}
__device__ __forceinline__ uint32_t f2tf32(float f) {
    uint32_t r;
    asm("cvt.rna.tf32.f32 %0, %1;" : "=r"(r) : "f"(f));
    return r;
}
__device__ __forceinline__ void mma_tf32(float* c, const uint32_t* a, const uint32_t* b) {
    asm volatile(
        "mma.sync.aligned.m16n8k8.row.col.f32.tf32.tf32.f32 "
        "{%0,%1,%2,%3}, {%4,%5,%6,%7}, {%8,%9}, {%0,%1,%2,%3};"
        : "+f"(c[0]), "+f"(c[1]), "+f"(c[2]), "+f"(c[3])
        : "r"(a[0]), "r"(a[1]), "r"(a[2]), "r"(a[3]),
          "r"(b[0]), "r"(b[1]));
}
__device__ __forceinline__ float gelu_exact(float x) {
    return 0.5f * x * (1.0f + erff(x * 0.7071067811865476f));
}

#define CP_ASYNC16(dst, src) \
    asm volatile("cp.async.cg.shared.global [%0], [%1], 16;" :: "r"(dst), "l"(src))
#define CP_COMMIT() asm volatile("cp.async.commit_group;" ::: "memory")
#define CP_WAIT1()  asm volatile("cp.async.wait_group 1;" ::: "memory")

// ---------------------------------------------------------------------------
// Kernel 1: router
// ---------------------------------------------------------------------------
__global__ void router_kernel(const float* __restrict__ x,
                              const float* __restrict__ gw,
                              float* __restrict__ logits_out) {
    int t = blockIdx.x;
    const float* xr = x + (size_t)t * HDIM;

    float acc[NEXP];
#pragma unroll
    for (int e = 0; e < NEXP; e++) acc[e] = 0.f;

    for (int h = threadIdx.x; h < HDIM; h += 256) {
        float xv = xr[h];
        const float4* g = (const float4*)(gw + (size_t)h * NEXP);
        float4 g0 = g[0], g1 = g[1];
        acc[0] += xv * g0.x; acc[1] += xv * g0.y;
        acc[2] += xv * g0.z; acc[3] += xv * g0.w;
        acc[4] += xv * g1.x; acc[5] += xv * g1.y;
        acc[6] += xv * g1.z; acc[7] += xv * g1.w;
    }

    __shared__ float sred[8][NEXP];
    int wid = threadIdx.x >> 5, lane = threadIdx.x & 31;
#pragma unroll
    for (int e = 0; e < NEXP; e++) {
        float v = acc[e];
#pragma unroll
        for (int o = 16; o > 0; o >>= 1) v += __shfl_down_sync(0xffffffffu, v, o);
        if (lane == 0) sred[wid][e] = v;
    }
    __syncthreads();

    if (threadIdx.x == 0) {
        float l[NEXP];
#pragma unroll
        for (int e = 0; e < NEXP; e++) {
            float s = 0.f;
#pragma unroll
            for (int w = 0; w < 8; w++) s += sred[w][e];
            l[e] = s;
            logits_out[(size_t)t * NEXP + e] = s;
        }
        int i0 = 0;
#pragma unroll
        for (int e = 1; e < NEXP; e++) if (l[e] > l[i0]) i0 = e;
        int i1 = -1;
#pragma unroll
        for (int e = 0; e < NEXP; e++) {
            if (e == i0) continue;
            if (i1 < 0 || l[e] > l[i1]) i1 = e;
        }
        float d = expf(l[i1] - l[i0]);
        float inv = 1.0f / (1.0f + d);
        g_sel[t * 2 + 0] = i0;  g_sel[t * 2 + 1] = i1;
        g_wts[t * 2 + 0] = inv; g_wts[t * 2 + 1] = d * inv;
    }
}

// ---------------------------------------------------------------------------
// Kernel 2: deterministic compaction
// ---------------------------------------------------------------------------
__global__ void compact_kernel() {
    int e = threadIdx.x >> 5;
    int lane = threadIdx.x & 31;
    __shared__ int scnt[NEXP], sbase[NEXP];

    int c = 0;
    for (int b = 0; b < T_TOK; b += 32) {
        int t = b + lane;
        bool f = (g_sel[t * 2] == e) || (g_sel[t * 2 + 1] == e);
        unsigned m = __ballot_sync(0xffffffffu, f);
        c += __popc(m);
    }
    if (lane == 0) scnt[e] = c;
    __syncthreads();
    if (threadIdx.x == 0) {
        int s = 0;
        for (int i = 0; i < NEXP; i++) { sbase[i] = s; s += scnt[i]; }
    }
    __syncthreads();
    int base = sbase[e];
    if (lane == 0) { g_cnt[e] = scnt[e]; g_basearr[e] = base; }

    c = 0;
    for (int b = 0; b < T_TOK; b += 32) {
        int t = b + lane;
        int s0 = g_sel[t * 2], s1 = g_sel[t * 2 + 1];
        bool f0 = (s0 == e), f1 = (s1 == e);
        bool f = f0 || f1;
        unsigned m = __ballot_sync(0xffffffffu, f);
        int off = c + __popc(m & ((1u << lane) - 1u));
        if (f) {
            g_tok[base + off] = t;
            g_slot_for[t * 2 + (f0 ? 0 : 1)] = base + off;
        }
        c += __popc(m);
    }
}

// ---------------------------------------------------------------------------
// Kernel 3/4: tf32 mma.sync GEMM
//   block 128(M) x 128(N) x 32(K), 4 warps (each 64x64), 3-stage cp.async.
//   A smem: [128][36] floats  (bank = 4*gid+tig, conflict-free)
//   B smem: [32][132] floats  (bank = 4*tig+gid, conflict-free)
//   smem/CTA = 106KB -> 2 CTAs per SM.
// ---------------------------------------------------------------------------
#define BM 128
#define BN 128
#define BK 32
#define A_ROW_F 36
#define B_ROW_F 132
#define A_BYTES (BM * A_ROW_F * 4)                 // 18432
#define B_OFF   A_BYTES
#define STAGE   (A_BYTES + BK * B_ROW_F * 4)       // 35328
#define NSTAGE  3
#define AROW_OFF (NSTAGE * STAGE)                  // 105984
#define SMEM_SZ (AROW_OFF + BM * 8)                // 107008

template <int KTOT, int NTOT, bool PASSA>
__global__ __launch_bounds__(128, 2) void gemm_cp(const float* __restrict__ Aglob,
                                                  const float* __restrict__ Bglob) {
    constexpr int NT = KTOT / BK;

    extern __shared__ char smem[];
    const int e = blockIdx.z;
    const int cnt = g_cnt[e];
    const int m0 = blockIdx.x * BM;
    if (m0 >= cnt) return;
    const int base = g_basearr[e];
    const int n0 = blockIdx.y * BN;
    const float* Bsrc = Bglob + (size_t)e * KTOT * NTOT;

    const uint32_t sb32 = smem_u32(smem);
    const int tid = threadIdx.x;

    // A-row pointer table in smem (8 rows/thread would burn registers)
    const float** arow = (const float**)(smem + AROW_OFF);
    {
        int r = m0 + tid;
        if (PASSA) {
            int tok = g_tok[base + ((r < cnt) ? r : 0)];
            arow[tid] = Aglob + (size_t)tok * KTOT;
        } else {
            int slot = base + ((r < cnt) ? r : 0);
            arow[tid] = g_hmid + (size_t)slot * KTOT;
        }
    }
    __syncthreads();

    // ---- loader geometry ----
    const int a_m  = tid >> 3;          // + i*16, i<8
    const int a_c8 = tid & 7;           // 16B chunk in 128B k-row
    const int b_k  = tid >> 5;          // + i*4, i<8
    const int b_c  = tid & 31;          // 16B chunk in 512B n-row

    auto issue = [&](int kt, int s) {
        uint32_t so = sb32 + s * STAGE;
        const int k0 = kt * BK;
#pragma unroll
        for (int i = 0; i < 8; i++) {
            int m = a_m + i * 16;
            CP_ASYNC16(so + (uint32_t)(m * (A_ROW_F * 4) + a_c8 * 16),
                       arow[m] + k0 + a_c8 * 4);
        }
        const float* bbase = Bsrc + (size_t)k0 * NTOT + n0 + b_c * 4;
#pragma unroll
        for (int i = 0; i < 8; i++) {
            int k = b_k + i * 4;
            CP_ASYNC16(so + (uint32_t)(B_OFF + k * (B_ROW_F * 4) + b_c * 16),
                       bbase + (size_t)k * NTOT);
        }
    };

    issue(0, 0); CP_COMMIT();
    issue(1, 1); CP_COMMIT();

    const int wid = tid >> 5, lane = tid & 31;
    const int wm = (wid & 1) * 64;
    const int wn = (wid >> 1) * 64;
    const int gid = lane >> 2, tig = lane & 3;

    float acc[4][8][4];
#pragma unroll
    for (int i = 0; i < 4; i++)
#pragma unroll
        for (int j = 0; j < 8; j++)
#pragma unroll
            for (int k = 0; k < 4; k++) acc[i][j][k] = 0.f;

#pragma unroll 1
    for (int kt = 0; kt < NT; kt++) {
        CP_WAIT1();              // stage kt resident
        __syncthreads();         // stage kt-1 reads complete; loads visible
        if (kt + 2 < NT) issue(kt + 2, (kt + 2) % NSTAGE);
        CP_COMMIT();

        const int s = kt % NSTAGE;
        const float* As = (const float*)(smem + s * STAGE);
        const float* Bs = (const float*)(smem + s * STAGE + B_OFF);

#pragma unroll
        for (int ks = 0; ks < 4; ks++) {
            const int kb = ks * 8;
            uint32_t af[4][4], bf[8][2];
#pragma unroll
            for (int ms = 0; ms < 4; ms++) {
                int am = wm + ms * 16 + gid;
                af[ms][0] = f2tf32(As[am * A_ROW_F + kb + tig]);
                af[ms][1] = f2tf32(As[(am + 8) * A_ROW_F + kb + tig]);
                af[ms][2] = f2tf32(As[am * A_ROW_F + kb + tig + 4]);
                af[ms][3] = f2tf32(As[(am + 8) * A_ROW_F + kb + tig + 4]);
            }
#pragma unroll
            for (int ns = 0; ns < 8; ns++) {
                int bn = wn + ns * 8 + gid;
                bf[ns][0] = f2tf32(Bs[(kb + tig) * B_ROW_F + bn]);
                bf[ns][1] = f2tf32(Bs[(kb + tig + 4) * B_ROW_F + bn]);
            }
#pragma unroll
            for (int ms = 0; ms < 4; ms++)
#pragma unroll
                for (int ns = 0; ns < 8; ns++)
                    mma_tf32(acc[ms][ns], af[ms], bf[ns]);
        }
    }

    // ---- epilogue: registers -> gmem ----
    float* Cg = PASSA ? g_hmid : g_y;
#pragma unroll
    for (int ms = 0; ms < 4; ms++) {
        int r0 = wm + ms * 16 + gid;
        int r1 = r0 + 8;
        bool ok0 = (m0 + r0) < cnt;
        bool ok1 = (m0 + r1) < cnt;
        size_t row0 = (size_t)(base + m0 + r0) * NTOT + n0;
        size_t row1 = (size_t)(base + m0 + r1) * NTOT + n0;
#pragma unroll
        for (int ns = 0; ns < 8; ns++) {
            int c = wn + ns * 8 + tig * 2;
            float v0 = acc[ms][ns][0], v1 = acc[ms][ns][1];
            float v2 = acc[ms][ns][2], v3 = acc[ms][ns][3];
            if (PASSA) {
                v0 = gelu_exact(v0); v1 = gelu_exact(v1);
                v2 = gelu_exact(v2); v3 = gelu_exact(v3);
            }
            if (ok0) *(float2*)(Cg + row0 + c) = make_float2(v0, v1);
            if (ok1) *(float2*)(Cg + row1 + c) = make_float2(v2, v3);
        }
    }
}

// ---------------------------------------------------------------------------
// Kernel 5: combine
// ---------------------------------------------------------------------------
__global__ void combine_kernel(const float* __restrict__ bias,
                               float* __restrict__ out) {
    int gid = blockIdx.x * 256 + threadIdx.x;
    if (gid >= T_TOK * (HDIM / 4)) return;
    int t = gid >> 9;
    int h4 = gid & 511;
    int s0 = g_slot_for[t * 2], s1 = g_slot_for[t * 2 + 1];
    float w0 = g_wts[t * 2], w1 = g_wts[t * 2 + 1];
    float4 y0 = *(const float4*)(g_y + (size_t)s0 * HDIM + h4 * 4);
    float4 y1 = *(const float4*)(g_y + (size_t)s1 * HDIM + h4 * 4);
    float4 b = *(const float4*)(bias + h4 * 4);
    float4 o;
    o.x = b.x + w0 * y0.x + w1 * y1.x;
    o.y = b.y + w0 * y0.y + w1 * y1.y;
    o.z = b.z + w0 * y0.z + w1 * y1.z;
    o.w = b.w + w0 * y0.w + w1 * y1.w;
    *(float4*)(out + (size_t)t * HDIM + h4 * 4) = o;
}

// ---------------------------------------------------------------------------
// launch
// ---------------------------------------------------------------------------
extern "C" void kernel_launch(void* const* d_in, const int* in_sizes, int n_in,
                              void* d_out, int out_size) {
    const float* x     = (const float*)d_in[0];   // [2,2048,2048]
    const float* gw    = (const float*)d_in[1];   // [2048,8]
    const float* w_in  = (const float*)d_in[2];   // [8,2048,8192]
    const float* w_out = (const float*)d_in[3];   // [8,8192,2048]
    const float* bias  = (const float*)d_in[4];   // [2048]
    (void)in_sizes; (void)n_in; (void)out_size;

    float* out    = (float*)d_out;
    float* logits = out + (size_t)T_TOK * HDIM;

    cudaFuncSetAttribute(gemm_cp<HDIM, IDIM, true>,
                         cudaFuncAttributeMaxDynamicSharedMemorySize, SMEM_SZ);
    cudaFuncSetAttribute(gemm_cp<IDIM, HDIM, false>,
                         cudaFuncAttributeMaxDynamicSharedMemorySize, SMEM_SZ);

    router_kernel<<<T_TOK, 256>>>(x, gw, logits);
    compact_kernel<<<1, 256>>>();

    dim3 ga(T_TOK / BM, IDIM / BN, NEXP);         // (32, 64, 8)
    gemm_cp<HDIM, IDIM, true><<<ga, 128, SMEM_SZ>>>(x, w_in);

    dim3 gb(T_TOK / BM, HDIM / BN, NEXP);         // (32, 16, 8)
    gemm_cp<IDIM, HDIM, false><<<gb, 128, SMEM_SZ>>>(nullptr, w_out);

    combine_kernel<<<(T_TOK * (HDIM / 4) + 255) / 256, 256>>>(bias, out);
}

// round 12
// speedup vs baseline: 1.4340x; 1.0003x over previous
#include <cuda_runtime.h>
#include <cstdint>

// ---------------------------------------------------------------------------
// SparseMoE: T=4096 tokens, H=2048, I=8192, E=8, top_k=2
// Round 7: occupancy fix. 128-thread CTAs (4 warps, 128x128 block tile,
// 64x64 warp tiles), 3-stage cp.async pipeline, 106KB smem -> 2 CTAs/SM.
// Two co-resident CTAs hide each other's barrier/pipeline stalls.
// ---------------------------------------------------------------------------

#define T_TOK 4096
#define HDIM  2048
#define IDIM  8192
#define NEXP  8
#define SLOTS 8192

__device__ float g_hmid[(size_t)SLOTS * IDIM];   // 256 MB
__device__ float g_y[(size_t)SLOTS * HDIM];      // 64 MB
__device__ int   g_tok[SLOTS];
__device__ int   g_slot_for[T_TOK * 2];
__device__ float g_wts[T_TOK * 2];
__device__ int   g_sel[T_TOK * 2];
__device__ int   g_cnt[NEXP];
__device__ int   g_basearr[NEXP];

// ---------------------------------------------------------------------------
// helpers
// ---------------------------------------------------------------------------
__device__ __forceinline__ uint32_t smem_u32(const void* p) {
    uint32_t a;
    asm("{ .reg .u64 t; cvta.to.shared.u64 t, %1; cvt.u32.u64 %0, t; }"
        : "=r"(a) : "l"(p));
    return a;
}
__device__ __forceinline__ uint32_t f2tf32(float f) {
    uint32_t r;
    asm("cvt.rna.tf32.f32 %0, %1;" : "=r"(r) : "f"(f));
    return r;
}
__device__ __forceinline__ void mma_tf32(float* c, const uint32_t* a, const uint32_t* b) {
    asm volatile(
        "mma.sync.aligned.m16n8k8.row.col.f32.tf32.tf32.f32 "
        "{%0,%1,%2,%3}, {%4,%5,%6,%7}, {%8,%9}, {%0,%1,%2,%3};"
        : "+f"(c[0]), "+f"(c[1]), "+f"(c[2]), "+f"(c[3])
        : "r"(a[0]), "r"(a[1]), "r"(a[2]), "r"(a[3]),
          "r"(b[0]), "r"(b[1]));
}
__device__ __forceinline__ float gelu_exact(float x) {
    return 0.5f * x * (1.0f + erff(x * 0.7071067811865476f));
}

#define CP_ASYNC16(dst, src) \
    asm volatile("cp.async.cg.shared.global [%0], [%1], 16;" :: "r"(dst), "l"(src))
#define CP_COMMIT() asm volatile("cp.async.commit_group;" ::: "memory")
#define CP_WAIT1()  asm volatile("cp.async.wait_group 1;" ::: "memory")

// ---------------------------------------------------------------------------
// Kernel 1: router
// ---------------------------------------------------------------------------
__global__ void router_kernel(const float* __restrict__ x,
                              const float* __restrict__ gw,
                              float* __restrict__ logits_out) {
    int t = blockIdx.x;
    const float* xr = x + (size_t)t * HDIM;

    float acc[NEXP];
#pragma unroll
    for (int e = 0; e < NEXP; e++) acc[e] = 0.f;

    for (int h = threadIdx.x; h < HDIM; h += 256) {
        float xv = xr[h];
        const float4* g = (const float4*)(gw + (size_t)h * NEXP);
        float4 g0 = g[0], g1 = g[1];
        acc[0] += xv * g0.x; acc[1] += xv * g0.y;
        acc[2] += xv * g0.z; acc[3] += xv * g0.w;
        acc[4] += xv * g1.x; acc[5] += xv * g1.y;
        acc[6] += xv * g1.z; acc[7] += xv * g1.w;
    }

    __shared__ float sred[8][NEXP];
    int wid = threadIdx.x >> 5, lane = threadIdx.x & 31;
#pragma unroll
    for (int e = 0; e < NEXP; e++) {
        float v = acc[e];
#pragma unroll
        for (int o = 16; o > 0; o >>= 1) v += __shfl_down_sync(0xffffffffu, v, o);
        if (lane == 0) sred[wid][e] = v;
    }
    __syncthreads();

    if (threadIdx.x == 0) {
        float l[NEXP];
#pragma unroll
        for (int e = 0; e < NEXP; e++) {
            float s = 0.f;
#pragma unroll
            for (int w = 0; w < 8; w++) s += sred[w][e];
            l[e] = s;
            logits_out[(size_t)t * NEXP + e] = s;
        }
        int i0 = 0;
#pragma unroll
        for (int e = 1; e < NEXP; e++) if (l[e] > l[i0]) i0 = e;
        int i1 = -1;
#pragma unroll
        for (int e = 0; e < NEXP; e++) {
            if (e == i0) continue;
            if (i1 < 0 || l[e] > l[i1]) i1 = e;
        }
        float d = expf(l[i1] - l[i0]);
        float inv = 1.0f / (1.0f + d);
        g_sel[t * 2 + 0] = i0;  g_sel[t * 2 + 1] = i1;
        g_wts[t * 2 + 0] = inv; g_wts[t * 2 + 1] = d * inv;
    }
}

// ---------------------------------------------------------------------------
// Kernel 2: deterministic compaction
// ---------------------------------------------------------------------------
__global__ void compact_kernel() {
    int e = threadIdx.x >> 5;
    int lane = threadIdx.x & 31;
    __shared__ int scnt[NEXP], sbase[NEXP];

    int c = 0;
    for (int b = 0; b < T_TOK; b += 32) {
        int t = b + lane;
        bool f = (g_sel[t * 2] == e) || (g_sel[t * 2 + 1] == e);
        unsigned m = __ballot_sync(0xffffffffu, f);
        c += __popc(m);
    }
    if (lane == 0) scnt[e] = c;
    __syncthreads();
    if (threadIdx.x == 0) {
        int s = 0;
        for (int i = 0; i < NEXP; i++) { sbase[i] = s; s += scnt[i]; }
    }
    __syncthreads();
    int base = sbase[e];
    if (lane == 0) { g_cnt[e] = scnt[e]; g_basearr[e] = base; }

    c = 0;
    for (int b = 0; b < T_TOK; b += 32) {
        int t = b + lane;
        int s0 = g_sel[t * 2], s1 = g_sel[t * 2 + 1];
        bool f0 = (s0 == e), f1 = (s1 == e);
        bool f = f0 || f1;
        unsigned m = __ballot_sync(0xffffffffu, f);
        int off = c + __popc(m & ((1u << lane) - 1u));
        if (f) {
            g_tok[base + off] = t;
            g_slot_for[t * 2 + (f0 ? 0 : 1)] = base + off;
        }
        c += __popc(m);
    }
}

// ---------------------------------------------------------------------------
// Kernel 3/4: tf32 mma.sync GEMM
//   block 128(M) x 128(N) x 32(K), 4 warps (each 64x64), 3-stage cp.async.
//   A smem: [128][36] floats  (bank = 4*gid+tig, conflict-free)
//   B smem: [32][132] floats  (bank = 4*tig+gid, conflict-free)
//   smem/CTA = 106KB -> 2 CTAs per SM.
// ---------------------------------------------------------------------------
#define BM 128
#define BN 128
#define BK 32
#define A_ROW_F 36
#define B_ROW_F 132
#define A_BYTES (BM * A_ROW_F * 4)                 // 18432
#define B_OFF   A_BYTES
#define STAGE   (A_BYTES + BK * B_ROW_F * 4)       // 35328
#define NSTAGE  3
#define AROW_OFF (NSTAGE * STAGE)                  // 105984
#define SMEM_SZ (AROW_OFF + BM * 8)                // 107008

template <int KTOT, int NTOT, bool PASSA>
__global__ __launch_bounds__(128, 2) void gemm_cp(const float* __restrict__ Aglob,
                                                  const float* __restrict__ Bglob) {
    constexpr int NT = KTOT / BK;

    extern __shared__ char smem[];
    const int e = blockIdx.z;
    const int cnt = g_cnt[e];
    const int m0 = blockIdx.x * BM;
    if (m0 >= cnt) return;
    const int base = g_basearr[e];
    const int n0 = blockIdx.y * BN;
    const float* Bsrc = Bglob + (size_t)e * KTOT * NTOT;

    const uint32_t sb32 = smem_u32(smem);
    const int tid = threadIdx.x;

    // A-row pointer table in smem (8 rows/thread would burn registers)
    const float** arow = (const float**)(smem + AROW_OFF);
    {
        int r = m0 + tid;
        if (PASSA) {
            int tok = g_tok[base + ((r < cnt) ? r : 0)];
            arow[tid] = Aglob + (size_t)tok * KTOT;
        } else {
            int slot = base + ((r < cnt) ? r : 0);
            arow[tid] = g_hmid + (size_t)slot * KTOT;
        }
    }
    __syncthreads();

    // ---- loader geometry ----
    const int a_m  = tid >> 3;          // + i*16, i<8
    const int a_c8 = tid & 7;           // 16B chunk in 128B k-row
    const int b_k  = tid >> 5;          // + i*4, i<8
    const int b_c  = tid & 31;          // 16B chunk in 512B n-row

    auto issue = [&](int kt, int s) {
        uint32_t so = sb32 + s * STAGE;
        const int k0 = kt * BK;
#pragma unroll
        for (int i = 0; i < 8; i++) {
            int m = a_m + i * 16;
            CP_ASYNC16(so + (uint32_t)(m * (A_ROW_F * 4) + a_c8 * 16),
                       arow[m] + k0 + a_c8 * 4);
        }
        const float* bbase = Bsrc + (size_t)k0 * NTOT + n0 + b_c * 4;
#pragma unroll
        for (int i = 0; i < 8; i++) {
            int k = b_k + i * 4;
            CP_ASYNC16(so + (uint32_t)(B_OFF + k * (B_ROW_F * 4) + b_c * 16),
                       bbase + (size_t)k * NTOT);
        }
    };

    issue(0, 0); CP_COMMIT();
    issue(1, 1); CP_COMMIT();

    const int wid = tid >> 5, lane = tid & 31;
    const int wm = (wid & 1) * 64;
    const int wn = (wid >> 1) * 64;
    const int gid = lane >> 2, tig = lane & 3;

    float acc[4][8][4];
#pragma unroll
    for (int i = 0; i < 4; i++)
#pragma unroll
        for (int j = 0; j < 8; j++)
#pragma unroll
            for (int k = 0; k < 4; k++) acc[i][j][k] = 0.f;

#pragma unroll 1
    for (int kt = 0; kt < NT; kt++) {
        CP_WAIT1();              // stage kt resident
        __syncthreads();         // stage kt-1 reads complete; loads visible
        if (kt + 2 < NT) issue(kt + 2, (kt + 2) % NSTAGE);
        CP_COMMIT();

        const int s = kt % NSTAGE;
        const float* As = (const float*)(smem + s * STAGE);
        const float* Bs = (const float*)(smem + s * STAGE + B_OFF);

#pragma unroll
        for (int ks = 0; ks < 4; ks++) {
            const int kb = ks * 8;
            uint32_t af[4][4], bf[8][2];
#pragma unroll
            for (int ms = 0; ms < 4; ms++) {
                int am = wm + ms * 16 + gid;
                af[ms][0] = f2tf32(As[am * A_ROW_F + kb + tig]);
                af[ms][1] = f2tf32(As[(am + 8) * A_ROW_F + kb + tig]);
                af[ms][2] = f2tf32(As[am * A_ROW_F + kb + tig + 4]);
                af[ms][3] = f2tf32(As[(am + 8) * A_ROW_F + kb + tig + 4]);
            }
#pragma unroll
            for (int ns = 0; ns < 8; ns++) {
                int bn = wn + ns * 8 + gid;
                bf[ns][0] = f2tf32(Bs[(kb + tig) * B_ROW_F + bn]);
                bf[ns][1] = f2tf32(Bs[(kb + tig + 4) * B_ROW_F + bn]);
            }
#pragma unroll
            for (int ms = 0; ms < 4; ms++)
#pragma unroll
                for (int ns = 0; ns < 8; ns++)
                    mma_tf32(acc[ms][ns], af[ms], bf[ns]);
        }
    }

    // ---- epilogue: registers -> gmem ----
    float* Cg = PASSA ? g_hmid : g_y;
#pragma unroll
    for (int ms = 0; ms < 4; ms++) {
        int r0 = wm + ms * 16 + gid;
        int r1 = r0 + 8;
        bool ok0 = (m0 + r0) < cnt;
        bool ok1 = (m0 + r1) < cnt;
        size_t row0 = (size_t)(base + m0 + r0) * NTOT + n0;
        size_t row1 = (size_t)(base + m0 + r1) * NTOT + n0;
#pragma unroll
        for (int ns = 0; ns < 8; ns++) {
            int c = wn + ns * 8 + tig * 2;
            float v0 = acc[ms][ns][0], v1 = acc[ms][ns][1];
            float v2 = acc[ms][ns][2], v3 = acc[ms][ns][3];
            if (PASSA) {
                v0 = gelu_exact(v0); v1 = gelu_exact(v1);
                v2 = gelu_exact(v2); v3 = gelu_exact(v3);
            }
            if (ok0) *(float2*)(Cg + row0 + c) = make_float2(v0, v1);
            if (ok1) *(float2*)(Cg + row1 + c) = make_float2(v2, v3);
        }
    }
}

// ---------------------------------------------------------------------------
// Kernel 5: combine
// ---------------------------------------------------------------------------
__global__ void combine_kernel(const float* __restrict__ bias,
                               float* __restrict__ out) {
    int gid = blockIdx.x * 256 + threadIdx.x;
    if (gid >= T_TOK * (HDIM / 4)) return;
    int t = gid >> 9;
    int h4 = gid & 511;
    int s0 = g_slot_for[t * 2], s1 = g_slot_for[t * 2 + 1];
    float w0 = g_wts[t * 2], w1 = g_wts[t * 2 + 1];
    float4 y0 = *(const float4*)(g_y + (size_t)s0 * HDIM + h4 * 4);
    float4 y1 = *(const float4*)(g_y + (size_t)s1 * HDIM + h4 * 4);
    float4 b = *(const float4*)(bias + h4 * 4);
    float4 o;
    o.x = b.x + w0 * y0.x + w1 * y1.x;
    o.y = b.y + w0 * y0.y + w1 * y1.y;
    o.z = b.z + w0 * y0.z + w1 * y1.z;
    o.w = b.w + w0 * y0.w + w1 * y1.w;
    *(float4*)(out + (size_t)t * HDIM + h4 * 4) = o;
}

// ---------------------------------------------------------------------------
// launch
// ---------------------------------------------------------------------------
extern "C" void kernel_launch(void* const* d_in, const int* in_sizes, int n_in,
                              void* d_out, int out_size) {
    const float* x     = (const float*)d_in[0];   // [2,2048,2048]
    const float* gw    = (const float*)d_in[1];   // [2048,8]
    const float* w_in  = (const float*)d_in[2];   // [8,2048,8192]
    const float* w_out = (const float*)d_in[3];   // [8,8192,2048]
    const float* bias  = (const float*)d_in[4];   // [2048]
    (void)in_sizes; (void)n_in; (void)out_size;

    float* out    = (float*)d_out;
    float* logits = out + (size_t)T_TOK * HDIM;

    cudaFuncSetAttribute(gemm_cp<HDIM, IDIM, true>,
                         cudaFuncAttributeMaxDynamicSharedMemorySize, SMEM_SZ);
    cudaFuncSetAttribute(gemm_cp<IDIM, HDIM, false>,
                         cudaFuncAttributeMaxDynamicSharedMemorySize, SMEM_SZ);

    router_kernel<<<T_TOK, 256>>>(x, gw, logits);
    compact_kernel<<<1, 256>>>();

    dim3 ga(T_TOK / BM, IDIM / BN, NEXP);         // (32, 64, 8)
    gemm_cp<HDIM, IDIM, true><<<ga, 128, SMEM_SZ>>>(x, w_in);

    dim3 gb(T_TOK / BM, HDIM / BN, NEXP);         // (32, 16, 8)
    gemm_cp<IDIM, HDIM, false><<<gb, 128, SMEM_SZ>>>(nullptr, w_out);

    combine_kernel<<<(T_TOK * (HDIM / 4) + 255) / 256, 256>>>(bias, out);
}